// round 3
// baseline (speedup 1.0000x reference)
#include <cuda_runtime.h>

// ---------------------------------------------------------------------------
// Allegro GNN layer, fp32, sm_103a.  Block-cooperative GEMM over 32-edge
// tiles: X K-major in smem [K][34], weights smem-resident (persistent blocks),
// thread tile = 2 edges x 8 outs, packed FFMA2 (out-pairs), red.global.v4
// scatters.
//   k_zero : zero env accumulators + output
//   k1g    : geometry+bessel+MLP(40->64->128) -> lat, Y, fcut
//   kenv0  : lat @ Wenv0 -> wedge store + env scatter
//   k2a    : channel products, s_mix, v_mix, scal0
//   k2bg   : [lat|scal0] MLP(192->128->128) + residual -> lat
//   k2cg   : lat @ Wenv1 -> env1 scatter
//   k3g    : [lat|q0|q1] MLP(192->128->128) + residual -> node scatter
// ---------------------------------------------------------------------------

#define NN 10000
#define NE 320000
#define NT32 10000      // NE/32
#define NT64 5000       // NE/64
typedef unsigned long long ULL;
typedef unsigned int U32;

__device__ float g_lat  [NE * 128];
__device__ float g_wedge[NE * 64];
__device__ float g_scal0[NE * 64];
__device__ float g_smix [NE * 32];
__device__ float g_vmix [NE * 128];   // [e][m][4] = {v0,v1,v2,0}
__device__ float g_Y    [NE * 4];
__device__ float g_fcut [NE];
__device__ float g_env  [NN * 128];
__device__ float g_env1 [NN * 128];

#define F_RS40      0.15811388300841897f
#define F_RS64      0.125f
#define F_RS96      0.10206207261596575f
#define F_RS128     0.08838834764831845f
#define F_RS192     0.07216878364870323f
#define F_ISN       0.17677669529663689f
#define F_SQRT3     1.7320508075688772f
#define F_INV_SQRT3 0.5773502691896258f
#define F_INV_SQRT2 0.7071067811865476f
#define F_C_OLD     0.8944271909999159f
#define F_C_NEW     0.4472135954999579f
#define F_BESSEL    0.6324555320336759f
#define F_PI        3.14159265358979323846f
#define F_INV_RMAX  0.2f

#define XPI  34     // X row pitch (BM=32)
#define XPI64 66    // X row pitch (BM=64, k2c)

__device__ __forceinline__ ULL fma2(ULL a, ULL b, ULL c) {
    ULL d;
    asm("fma.rn.f32x2 %0, %1, %2, %3;" : "=l"(d) : "l"(a), "l"(b), "l"(c));
    return d;
}
__device__ __forceinline__ ULL pack2(float x) {
    ULL d; U32 u = __float_as_uint(x);
    asm("mov.b64 %0, {%1,%1};" : "=l"(d) : "r"(u));
    return d;
}
__device__ __forceinline__ void red4(float* p, float a, float b, float c, float d) {
    asm volatile("red.global.add.v4.f32 [%0], {%1,%2,%3,%4};"
                 :: "l"(p), "f"(a), "f"(b), "f"(c), "f"(d) : "memory");
}
__device__ __forceinline__ float silu_f(float v) {
    return v * __frcp_rn(1.0f + __expf(-v));
}

// ---------------------------------------------------------------------------
// Block GEMM tile: thread computes 2 edges (2eg, 2eg+1) x OPT outs (OPT*og..)
// X: [K][XP] K-major, W: [K][OUT] row-major, both smem.  Out-pair FFMA2.
// ---------------------------------------------------------------------------
template <int K, int OUT, int OPT, int XP, bool SILU>
__device__ __forceinline__ void gemm_t(
    const float* __restrict__ X, const float* __restrict__ W,
    int eg, int og, float sc0, float sc1, float res[2][OPT])
{
    constexpr int NP = OPT / 2;
    ULL acc[2][NP];
#pragma unroll
    for (int e = 0; e < 2; e++)
#pragma unroll
        for (int p = 0; p < NP; p++) acc[e][p] = 0ULL;

    const float* xp = X + 2 * eg;
    const float* wp = W + OPT * og;
#pragma unroll 4
    for (int k = 0; k < K; k++) {
        float2 xv = *reinterpret_cast<const float2*>(xp + k * XP);
        ULL x0 = pack2(xv.x);
        ULL x1 = pack2(xv.y);
        ULL w[NP];
        if constexpr (OPT == 8) {
            ulonglong2 wa = *reinterpret_cast<const ulonglong2*>(wp + k * OUT);
            ulonglong2 wb = *reinterpret_cast<const ulonglong2*>(wp + k * OUT + 4);
            w[0] = wa.x; w[1] = wa.y; w[2] = wb.x; w[3] = wb.y;
        } else {
            ulonglong2 wa = *reinterpret_cast<const ulonglong2*>(wp + k * OUT);
            w[0] = wa.x; w[1] = wa.y;
        }
#pragma unroll
        for (int p = 0; p < NP; p++) {
            acc[0][p] = fma2(x0, w[p], acc[0][p]);
            acc[1][p] = fma2(x1, w[p], acc[1][p]);
        }
    }
#pragma unroll
    for (int e = 0; e < 2; e++) {
        float s = e ? sc1 : sc0;
#pragma unroll
        for (int p = 0; p < NP; p++) {
            union { ULL u; float2 f; } cv; cv.u = acc[e][p];
            float a = cv.f.x * s, b = cv.f.y * s;
            if (SILU) { a = silu_f(a); b = silu_f(b); }
            res[e][2 * p]     = a;
            res[e][2 * p + 1] = b;
        }
    }
}

template <int OPT, int XP>
__device__ __forceinline__ void storeH(float* __restrict__ H, int eg, int og,
                                       float res[2][OPT])
{
#pragma unroll
    for (int o = 0; o < OPT; o++) {
        *reinterpret_cast<float2*>(H + (OPT * og + o) * XP + 2 * eg) =
            make_float2(res[0][o], res[1][o]);
    }
}

// ---------------------------------------------------------------------------
__global__ void k_zero(float* __restrict__ out)
{
    int i = blockIdx.x * blockDim.x + threadIdx.x;
    int stride = gridDim.x * blockDim.x;
    for (; i < NN * 128; i += stride) {
        g_env[i]  = 0.0f;
        g_env1[i] = 0.0f;
        out[i]    = 0.0f;
    }
}

// ---------------------------------------------------------------------------
// K1: geometry + bessel + 40->64->128->128(lat).  BM=32.
// smem: W0 2560 | W1 8192 | W2 16384 | X 40*34 | H1 64*34 | H2 128*34 | meta
// ---------------------------------------------------------------------------
__global__ void __launch_bounds__(256, 1) k1g(
    const float* __restrict__ coords, const float* __restrict__ attrs,
    const int*   __restrict__ eidx,
    const float* __restrict__ W2b0, const float* __restrict__ W2b1,
    const float* __restrict__ W2b2)
{
    extern __shared__ __align__(16) float sh[];
    float* sW0 = sh;                    // 2560
    float* sW1 = sW0 + 2560;            // 8192
    float* sW2 = sW1 + 8192;            // 16384
    float* X   = sW2 + 16384;           // 40*34  = 1360
    float* H1  = X   + 1360;            // 64*34  = 2176
    float* H2  = H1  + 2176;            // 128*34 = 4352
    float* s_u    = H2 + 4352;          // 32
    float* s_ir   = s_u + 32;           // 32
    float* s_fc   = s_ir + 32;          // 32
    int*   s_ctr  = (int*)(s_fc + 32);  // 32
    int*   s_snd  = s_ctr + 32;         // 32

    int tid = threadIdx.x;
    for (int i = tid; i < 2560;  i += 256) sW0[i] = W2b0[i];
    for (int i = tid; i < 8192;  i += 256) sW1[i] = W2b1[i];
    for (int i = tid; i < 16384; i += 256) sW2[i] = W2b2[i];
    __syncthreads();

    int eg = tid & 15, og = tid >> 4;

    for (int t = blockIdx.x; t < NT32; t += gridDim.x) {
        int e0 = t * 32;
        __syncthreads();
        if (tid < 32) {
            int e = e0 + tid;
            int snd = eidx[e];
            int c   = eidx[NE + e];
            s_ctr[tid] = c; s_snd[tid] = snd;
            float dx = coords[c * 3 + 0] - coords[snd * 3 + 0];
            float dy = coords[c * 3 + 1] - coords[snd * 3 + 1];
            float dz = coords[c * 3 + 2] - coords[snd * 3 + 2];
            float r2 = dx * dx + dy * dy + dz * dz + 1e-12f;
            float r  = sqrtf(r2);
            float inv_r = 1.0f / r;
            float u  = r * F_INV_RMAX;
            float u2 = u * u, u3 = u2 * u, u6 = u3 * u3, u7 = u6 * u, u8 = u7 * u;
            float f  = 1.0f - 28.0f * u6 + 48.0f * u7 - 21.0f * u8;
            if (u >= 1.0f) f = 0.0f;
            s_u[tid] = u; s_ir[tid] = inv_r; s_fc[tid] = f;
            g_fcut[e] = f;
            *reinterpret_cast<float4*>(&g_Y[e * 4]) =
                make_float4(1.0f, F_SQRT3 * dx * inv_r,
                            F_SQRT3 * dy * inv_r, F_SQRT3 * dz * inv_r);
        }
        __syncthreads();
        // attrs rows 0..31
        for (int id = tid; id < 1024; id += 256) {
            int r = id & 31, e = id >> 5;
            float v = (r < 16) ? attrs[s_ctr[e] * 16 + r]
                               : attrs[s_snd[e] * 16 + (r - 16)];
            X[r * XPI + e] = v;
        }
        // bessel rows 32..39
        {
            int e = tid >> 3, n = tid & 7;
            float b = F_BESSEL * sinf((n + 1) * F_PI * s_u[e]) * s_ir[e] * s_fc[e];
            X[(32 + n) * XPI + e] = b;
        }
        __syncthreads();

        float r1[2][4];
        gemm_t<40, 64, 4, XPI, true>(X, sW0, eg, og, F_RS40, F_RS40, r1);
        storeH<4, XPI>(H1, eg, og, r1);
        __syncthreads();

        float r2[2][8];
        gemm_t<64, 128, 8, XPI, true>(H1, sW1, eg, og, F_RS64, F_RS64, r2);
        storeH<8, XPI>(H2, eg, og, r2);
        __syncthreads();

        float r3[2][8];
        gemm_t<128, 128, 8, XPI, false>(H2, sW2, eg, og,
                                        F_RS128 * s_fc[2 * eg],
                                        F_RS128 * s_fc[2 * eg + 1], r3);
#pragma unroll
        for (int j = 0; j < 2; j++) {
            long e = e0 + 2 * eg + j;
            *reinterpret_cast<float4*>(&g_lat[e * 128 + 8 * og]) =
                make_float4(r3[j][0], r3[j][1], r3[j][2], r3[j][3]);
            *reinterpret_cast<float4*>(&g_lat[e * 128 + 8 * og + 4]) =
                make_float4(r3[j][4], r3[j][5], r3[j][6], r3[j][7]);
        }
    }
}

// ---------------------------------------------------------------------------
// KENV0: w_all = lat @ Wenv0 (128->128); wedge store + env scatter.  BM=32.
// ---------------------------------------------------------------------------
__global__ void __launch_bounds__(256, 1) kenv0(
    const int* __restrict__ eidx, const float* __restrict__ Wenv0)
{
    extern __shared__ __align__(16) float sh[];
    float*  sW   = sh;                    // 16384
    float*  X    = sW + 16384;            // 4352
    float4* s_Y  = (float4*)(X + 4352);   // 32 float4 = 128
    int*    s_ctr = (int*)(s_Y + 32);     // 32

    int tid = threadIdx.x;
    for (int i = tid; i < 16384; i += 256) sW[i] = Wenv0[i];
    __syncthreads();

    int eg = tid & 15, og = tid >> 4;

    for (int t = blockIdx.x; t < NT32; t += gridDim.x) {
        int e0 = t * 32;
        __syncthreads();
        if (tid < 32) {
            s_ctr[tid] = eidx[NE + e0 + tid];
            s_Y[tid]   = *reinterpret_cast<const float4*>(&g_Y[(e0 + tid) * 4]);
        }
        for (int id = tid; id < 4096; id += 256) {
            int k = id & 127, e = id >> 7;
            X[k * XPI + e] = g_lat[(long)(e0 + e) * 128 + k];
        }
        __syncthreads();

        float r[2][8];
        gemm_t<128, 128, 8, XPI, false>(X, sW, eg, og, F_RS128, F_RS128, r);

#pragma unroll
        for (int j = 0; j < 2; j++) {
            int el = 2 * eg + j;
            long e = e0 + el;
            if (og < 8) {
                *reinterpret_cast<float4*>(&g_wedge[e * 64 + 8 * og]) =
                    make_float4(r[j][0], r[j][1], r[j][2], r[j][3]);
                *reinterpret_cast<float4*>(&g_wedge[e * 64 + 8 * og + 4]) =
                    make_float4(r[j][4], r[j][5], r[j][6], r[j][7]);
            } else {
                long c = s_ctr[el];
                float4 Y = s_Y[el];
#pragma unroll
                for (int p = 0; p < 4; p++) {
                    int m = 4 * (og - 8) + p;
                    float w0 = r[j][2 * p], w1 = r[j][2 * p + 1];
                    red4(&g_env[c * 128 + 4 * m], w0, w1 * Y.y, w1 * Y.z, w1 * Y.w);
                }
            }
        }
    }
}

// ---------------------------------------------------------------------------
// K2a: equivariant products + s_mix + v_mix + scal0 (lane == channel m)
// ---------------------------------------------------------------------------
__global__ void __launch_bounds__(256) k2a(
    const int* __restrict__ eidx,
    const float* __restrict__ Ws0, const float* __restrict__ Wv0)
{
    __shared__ __align__(16) float sWs [64 * 32];
    __shared__ __align__(16) float sWvD[96 * 32 * 2];
    __shared__ __align__(16) float stage[8][64];
    __shared__ __align__(16) float Pst[8][96 * 4];

    int tid = threadIdx.x;
    for (int i = tid; i < 64 * 32; i += 256) sWs[i] = Ws0[i];
    for (int i = tid; i < 96 * 32; i += 256) {
        float w = Wv0[i];
        sWvD[2 * i] = w; sWvD[2 * i + 1] = w;
    }
    __syncthreads();

    int warp = tid >> 5, lane = tid & 31;
    int gw = blockIdx.x * 8 + warp;
    int nw = gridDim.x * 8;

    for (int e = gw; e < NE; e += nw) {
        int c = eidx[NE + e];
        float2 we = *reinterpret_cast<const float2*>(&g_wedge[e * 64 + 2 * lane]);
        float4 en = *reinterpret_cast<const float4*>(&g_env[(long)c * 128 + 4 * lane]);
        float4 Yv = *reinterpret_cast<const float4*>(&g_Y[e * 4]);
        float fs  = we.x;
        float fv0 = we.y * Yv.y, fv1 = we.y * Yv.z, fv2 = we.y * Yv.w;
        float es  = en.x * F_ISN;
        float ev0 = en.y * F_ISN, ev1 = en.z * F_ISN, ev2 = en.w * F_ISN;

        float p0 = fs * es;
        float p1 = (fv0 * ev0 + fv1 * ev1 + fv2 * ev2) * F_INV_SQRT3;
        stage[warp][lane]      = p0;
        stage[warp][32 + lane] = p1;
        float* P = Pst[warp];
        *reinterpret_cast<float4*>(P + lane * 4) =
            make_float4(fs * ev0, fs * ev1, fs * ev2, 0.0f);
        *reinterpret_cast<float4*>(P + (32 + lane) * 4) =
            make_float4(fv0 * es, fv1 * es, fv2 * es, 0.0f);
        *reinterpret_cast<float4*>(P + (64 + lane) * 4) =
            make_float4((fv1 * ev2 - fv2 * ev1) * F_INV_SQRT2,
                        (fv2 * ev0 - fv0 * ev2) * F_INV_SQRT2,
                        (fv0 * ev1 - fv1 * ev0) * F_INV_SQRT2, 0.0f);
        __syncwarp();

        float sm = 0.0f;
#pragma unroll 4
        for (int i = 0; i < 64; i++) sm = fmaf(stage[warp][i], sWs[i * 32 + lane], sm);
        sm *= F_RS64;

        ULL a01 = 0ULL, a2x = 0ULL;
#pragma unroll 4
        for (int i = 0; i < 96; i++) {
            ULL wd = *reinterpret_cast<const ULL*>(sWvD + (i * 32 + lane) * 2);
            ulonglong2 pp = *reinterpret_cast<const ulonglong2*>(P + i * 4);
            a01 = fma2(pp.x, wd, a01);
            a2x = fma2(pp.y, wd, a2x);
        }
        union { ULL u; float2 f; } c01, c2x;
        c01.u = a01; c2x.u = a2x;

        g_scal0[e * 64 + lane]      = p0;
        g_scal0[e * 64 + 32 + lane] = p1;
        g_smix[e * 32 + lane] = sm;
        *reinterpret_cast<float4*>(&g_vmix[(long)e * 128 + 4 * lane]) =
            make_float4(c01.f.x * F_RS96, c01.f.y * F_RS96, c2x.f.x * F_RS96, 0.0f);
        __syncwarp();
    }
}

// ---------------------------------------------------------------------------
// K2b: [lat|scal0] 192->128 silu ->128 (*fcut) + residual -> lat.  BM=32.
// ---------------------------------------------------------------------------
__global__ void __launch_bounds__(256, 1) k2bg(
    const float* __restrict__ Wlat0, const float* __restrict__ Wlat1)
{
    extern __shared__ __align__(16) float sh[];
    float* sW0 = sh;                 // 24576
    float* sW1 = sW0 + 24576;        // 16384
    float* X   = sW1 + 16384;        // 192*34 = 6528
    float* H   = X   + 6528;         // 128*34 = 4352
    float* s_fc = H + 4352;          // 32

    int tid = threadIdx.x;
    for (int i = tid; i < 24576; i += 256) sW0[i] = Wlat0[i];
    for (int i = tid; i < 16384; i += 256) sW1[i] = Wlat1[i];
    __syncthreads();

    int eg = tid & 15, og = tid >> 4;

    for (int t = blockIdx.x; t < NT32; t += gridDim.x) {
        int e0 = t * 32;
        __syncthreads();
        if (tid < 32) s_fc[tid] = g_fcut[e0 + tid];
        for (int id = tid; id < 4096; id += 256) {
            int k = id & 127, e = id >> 7;
            X[k * XPI + e] = g_lat[(long)(e0 + e) * 128 + k];
        }
        for (int id = tid; id < 2048; id += 256) {
            int k = id & 63, e = id >> 6;
            X[(128 + k) * XPI + e] = g_scal0[(long)(e0 + e) * 64 + k];
        }
        __syncthreads();

        float r0[2][8];
        gemm_t<192, 128, 8, XPI, true>(X, sW0, eg, og, F_RS192, F_RS192, r0);
        storeH<8, XPI>(H, eg, og, r0);
        __syncthreads();

        float r1[2][8];
        gemm_t<128, 128, 8, XPI, false>(H, sW1, eg, og,
                                        F_RS128 * s_fc[2 * eg],
                                        F_RS128 * s_fc[2 * eg + 1], r1);
#pragma unroll
        for (int j = 0; j < 2; j++) {
            long e = e0 + 2 * eg + j;
            float4 l0 = *reinterpret_cast<float4*>(&g_lat[e * 128 + 8 * og]);
            float4 l1 = *reinterpret_cast<float4*>(&g_lat[e * 128 + 8 * og + 4]);
            *reinterpret_cast<float4*>(&g_lat[e * 128 + 8 * og]) =
                make_float4(F_C_OLD * l0.x + F_C_NEW * r1[j][0],
                            F_C_OLD * l0.y + F_C_NEW * r1[j][1],
                            F_C_OLD * l0.z + F_C_NEW * r1[j][2],
                            F_C_OLD * l0.w + F_C_NEW * r1[j][3]);
            *reinterpret_cast<float4*>(&g_lat[e * 128 + 8 * og + 4]) =
                make_float4(F_C_OLD * l1.x + F_C_NEW * r1[j][4],
                            F_C_OLD * l1.y + F_C_NEW * r1[j][5],
                            F_C_OLD * l1.z + F_C_NEW * r1[j][6],
                            F_C_OLD * l1.w + F_C_NEW * r1[j][7]);
        }
    }
}

// ---------------------------------------------------------------------------
// K2c: w_env1 = lat @ Wenv1 (128->64) + env1 scatter.  BM=64.
// ---------------------------------------------------------------------------
__global__ void __launch_bounds__(256, 1) k2cg(
    const int* __restrict__ eidx, const float* __restrict__ Wenv1)
{
    extern __shared__ __align__(16) float sh[];
    float*  sW    = sh;                    // 8192
    float*  X     = sW + 8192;             // 128*66 = 8448
    float4* s_Y   = (float4*)(X + 8448);   // 64 float4 = 256
    int*    s_ctr = (int*)(s_Y + 64);      // 64

    int tid = threadIdx.x;
    for (int i = tid; i < 8192; i += 256) sW[i] = Wenv1[i];
    __syncthreads();

    int eg = tid & 31, og = tid >> 5;

    for (int t = blockIdx.x; t < NT64; t += gridDim.x) {
        int e0 = t * 64;
        __syncthreads();
        if (tid < 64) {
            s_ctr[tid] = eidx[NE + e0 + tid];
            s_Y[tid]   = *reinterpret_cast<const float4*>(&g_Y[(e0 + tid) * 4]);
        }
        for (int id = tid; id < 8192; id += 256) {
            int k = id & 127, e = id >> 7;
            X[k * XPI64 + e] = g_lat[(long)(e0 + e) * 128 + k];
        }
        __syncthreads();

        float r[2][8];
        gemm_t<128, 64, 8, XPI64, false>(X, sW, eg, og, F_RS128, F_RS128, r);

#pragma unroll
        for (int j = 0; j < 2; j++) {
            int el = 2 * eg + j;
            long c = s_ctr[el];
            float4 Y = s_Y[el];
#pragma unroll
            for (int p = 0; p < 4; p++) {
                int m = 4 * og + p;
                float w0 = r[j][2 * p], w1 = r[j][2 * p + 1];
                red4(&g_env1[c * 128 + 4 * m], w0, w1 * Y.y, w1 * Y.z, w1 * Y.w);
            }
        }
    }
}

// ---------------------------------------------------------------------------
// K3: [lat|q0|q1] 192->128 silu ->128 (*fcut) + residual -> node scatter.
// ---------------------------------------------------------------------------
__global__ void __launch_bounds__(256, 1) k3g(
    const int*   __restrict__ eidx,
    const float* __restrict__ Wfin0, const float* __restrict__ Wfin1,
    float* __restrict__ out)
{
    extern __shared__ __align__(16) float sh[];
    float* sW0  = sh;                 // 24576
    float* sW1  = sW0 + 24576;        // 16384
    float* X    = sW1 + 16384;        // 6528
    float* H    = X   + 6528;         // 4352
    float* s_fc = H + 4352;           // 32
    int*   s_ctr = (int*)(s_fc + 32); // 32

    int tid = threadIdx.x;
    for (int i = tid; i < 24576; i += 256) sW0[i] = Wfin0[i];
    for (int i = tid; i < 16384; i += 256) sW1[i] = Wfin1[i];
    __syncthreads();

    int eg = tid & 15, og = tid >> 4;

    for (int t = blockIdx.x; t < NT32; t += gridDim.x) {
        int e0 = t * 32;
        __syncthreads();
        if (tid < 32) {
            s_fc[tid]  = g_fcut[e0 + tid];
            s_ctr[tid] = eidx[NE + e0 + tid];
        }
        __syncthreads();
        for (int id = tid; id < 4096; id += 256) {
            int k = id & 127, e = id >> 7;
            X[k * XPI + e] = g_lat[(long)(e0 + e) * 128 + k];
        }
        // q0/q1 rows 128..191
        for (int id = tid; id < 1024; id += 256) {
            int m = id & 31, e = id >> 5;
            long ge = e0 + e;
            long c  = s_ctr[e];
            float4 e1 = *reinterpret_cast<const float4*>(&g_env1[c * 128 + 4 * m]);
            float4 vm = *reinterpret_cast<const float4*>(&g_vmix[ge * 128 + 4 * m]);
            float sm  = g_smix[ge * 32 + m];
            float q0 = sm * e1.x * F_ISN;
            float q1 = (vm.x * e1.y + vm.y * e1.z + vm.z * e1.w) * F_ISN * F_INV_SQRT3;
            X[(128 + m) * XPI + e] = q0;
            X[(160 + m) * XPI + e] = q1;
        }
        __syncthreads();

        float r0[2][8];
        gemm_t<192, 128, 8, XPI, true>(X, sW0, eg, og, F_RS192, F_RS192, r0);
        storeH<8, XPI>(H, eg, og, r0);
        __syncthreads();

        float r1[2][8];
        gemm_t<128, 128, 8, XPI, false>(H, sW1, eg, og,
                                        F_RS128 * s_fc[2 * eg],
                                        F_RS128 * s_fc[2 * eg + 1], r1);
#pragma unroll
        for (int j = 0; j < 2; j++) {
            int el = 2 * eg + j;
            long e = e0 + el;
            long c = s_ctr[el];
            float4 l0 = *reinterpret_cast<float4*>(&g_lat[e * 128 + 8 * og]);
            float4 l1 = *reinterpret_cast<float4*>(&g_lat[e * 128 + 8 * og + 4]);
            red4(&out[c * 128 + 8 * og],
                 (F_C_OLD * l0.x + F_C_NEW * r1[j][0]) * F_ISN,
                 (F_C_OLD * l0.y + F_C_NEW * r1[j][1]) * F_ISN,
                 (F_C_OLD * l0.z + F_C_NEW * r1[j][2]) * F_ISN,
                 (F_C_OLD * l0.w + F_C_NEW * r1[j][3]) * F_ISN);
            red4(&out[c * 128 + 8 * og + 4],
                 (F_C_OLD * l1.x + F_C_NEW * r1[j][4]) * F_ISN,
                 (F_C_OLD * l1.y + F_C_NEW * r1[j][5]) * F_ISN,
                 (F_C_OLD * l1.z + F_C_NEW * r1[j][6]) * F_ISN,
                 (F_C_OLD * l1.w + F_C_NEW * r1[j][7]) * F_ISN);
        }
    }
}

// ---------------------------------------------------------------------------
extern "C" void kernel_launch(void* const* d_in, const int* in_sizes, int n_in,
                              void* d_out, int out_size)
{
    const float* coords = (const float*)d_in[0];
    const float* attrs  = (const float*)d_in[1];
    const int*   eidx   = (const int*)  d_in[2];
    const float* W2b0   = (const float*)d_in[3];
    const float* W2b1   = (const float*)d_in[4];
    const float* W2b2   = (const float*)d_in[5];
    const float* Wenv0  = (const float*)d_in[6];
    const float* Wlat0  = (const float*)d_in[7];
    const float* Wlat1  = (const float*)d_in[8];
    const float* Ws0    = (const float*)d_in[9];
    const float* Wv0    = (const float*)d_in[10];
    const float* Wenv1  = (const float*)d_in[11];
    const float* Wfin0  = (const float*)d_in[12];
    const float* Wfin1  = (const float*)d_in[13];
    float* out = (float*)d_out;

    const size_t sm_k1  = (2560 + 8192 + 16384 + 1360 + 2176 + 4352 + 160 + 16) * 4;
    const size_t sm_ke  = (16384 + 4352 + 128 + 32 + 16) * 4;
    const size_t sm_k2b = (24576 + 16384 + 6528 + 4352 + 32 + 16) * 4;
    const size_t sm_k2c = (8192 + 8448 + 256 + 64 + 16) * 4;
    const size_t sm_k3  = (24576 + 16384 + 6528 + 4352 + 64 + 16) * 4;

    static int configured = 0;
    cudaFuncSetAttribute(k1g,  cudaFuncAttributeMaxDynamicSharedMemorySize, (int)sm_k1);
    cudaFuncSetAttribute(kenv0,cudaFuncAttributeMaxDynamicSharedMemorySize, (int)sm_ke);
    cudaFuncSetAttribute(k2bg, cudaFuncAttributeMaxDynamicSharedMemorySize, (int)sm_k2b);
    cudaFuncSetAttribute(k2cg, cudaFuncAttributeMaxDynamicSharedMemorySize, (int)sm_k2c);
    cudaFuncSetAttribute(k3g,  cudaFuncAttributeMaxDynamicSharedMemorySize, (int)sm_k3);
    (void)configured;

    k_zero<<<512, 256>>>(out);
    k1g  <<<148, 256, sm_k1 >>>(coords, attrs, eidx, W2b0, W2b1, W2b2);
    kenv0<<<148, 256, sm_ke >>>(eidx, Wenv0);
    k2a  <<<592, 256>>>(eidx, Ws0, Wv0);
    k2bg <<<148, 256, sm_k2b>>>(Wlat0, Wlat1);
    k2cg <<<148, 256, sm_k2c>>>(eidx, Wenv1);
    k3g  <<<148, 256, sm_k3 >>>(eidx, Wfin0, Wfin1, out);
}

// round 4
// speedup vs baseline: 1.6662x; 1.6662x over previous
#include <cuda_runtime.h>

// ---------------------------------------------------------------------------
// Allegro GNN layer as 11 streaming FFMA2 GEMMs + 3 elementwise kernels.
// Each GEMM: persistent 148 blocks x 512 threads, weights in smem, activations
// staged e-major via cp.async in double-buffered K-chunks, thread tile
// 4 edges x 8 outs (or variants), packed fma.rn.f32x2.
// ---------------------------------------------------------------------------

#define NN 10000
#define NE 320000
#define NE3 960000
typedef unsigned long long ULL;

__device__ float g_X0  [NE * 40];
__device__ float g_H1  [NE * 64];
__device__ float g_H   [NE * 128];
__device__ float g_lat [NE * 128];
__device__ float g_wedge[NE * 64];
__device__ float g_scal0[NE * 64];
__device__ float g_P   [(long)NE3 * 96];
__device__ float g_smix[NE * 32];
__device__ float g_vmx [NE3 * 32];
__device__ float g_q   [NE * 64];
__device__ float g_Y   [NE * 4];
__device__ float g_fcut[NE];
__device__ float g_env [NN * 128];
__device__ float g_env1[NN * 128];

#define F_RS40      0.15811388300841897f
#define F_RS64      0.125f
#define F_RS96      0.10206207261596575f
#define F_RS128     0.08838834764831845f
#define F_RS192     0.07216878364870323f
#define F_ISN       0.17677669529663689f
#define F_SQRT3     1.7320508075688772f
#define F_INV_SQRT3 0.5773502691896258f
#define F_INV_SQRT2 0.7071067811865476f
#define F_C_OLD     0.8944271909999159f
#define F_C_NEW     0.4472135954999579f
#define F_BESSEL    0.6324555320336759f
#define F_PI        3.14159265358979323846f
#define F_INV_RMAX  0.2f

__device__ __forceinline__ ULL fma2(ULL a, ULL b, ULL c) {
    ULL d;
    asm("fma.rn.f32x2 %0, %1, %2, %3;" : "=l"(d) : "l"(a), "l"(b), "l"(c));
    return d;
}
__device__ __forceinline__ ULL pack2(float x) {
    ULL d; unsigned u = __float_as_uint(x);
    asm("mov.b64 %0, {%1,%1};" : "=l"(d) : "r"(u));
    return d;
}
__device__ __forceinline__ void red4(float* p, float a, float b, float c, float d) {
    asm volatile("red.global.add.v4.f32 [%0], {%1,%2,%3,%4};"
                 :: "l"(p), "f"(a), "f"(b), "f"(c), "f"(d) : "memory");
}
__device__ __forceinline__ float silu_f(float v) {
    return v * __frcp_rn(1.0f + __expf(-v));
}
__device__ __forceinline__ void cpa16(const void* s, const void* g) {
    unsigned sa = (unsigned)__cvta_generic_to_shared(s);
    asm volatile("cp.async.cg.shared.global [%0], [%1], 16;" :: "r"(sa), "l"(g));
}
__device__ __forceinline__ void cp_commit() { asm volatile("cp.async.commit_group;"); }
__device__ __forceinline__ void cp_wait1()  { asm volatile("cp.async.wait_group 1;"); }
__device__ __forceinline__ void cp_wait0()  { asm volatile("cp.async.wait_group 0;"); }

// ---------------------------------------------------------------------------
// Generic streaming GEMM.  BM=128 edge rows per tile.
//   OUT=128: OPO=8, 16 og x (32 eg x 4 edges)
//   OUT=64 : OPO=4, 16 og x (32 eg x 4 edges)
//   OUT=32 : OPO=4,  8 og x (64 eg x 2 edges)
// ---------------------------------------------------------------------------
template <int KTOT, int KC, int OUT, int OPO, class Op>
__global__ void __launch_bounds__(512, 1) gk(Op op, const float* __restrict__ Wg,
                                             int ntiles)
{
    constexpr int PC  = KC + 4;           // PC % 8 == 4 -> conflict-free
    constexpr int NCH = KTOT / KC;
    constexpr int OG  = OUT / OPO;
    constexpr int OGW = OG / 4;           // warps along og
    constexpr int EGN = 512 / OG;         // 32 or 64 eg values
    constexpr int EPT = 128 / EGN;        // 4 or 2 edges per thread
    constexpr int NP  = OPO / 2;

    extern __shared__ __align__(16) float sh[];
    float* sW = sh;                        // KTOT*OUT
    float* sX = sh + KTOT * OUT;           // 2 * 128 * PC

    int tid = threadIdx.x;
    for (int i = tid; i < KTOT * OUT / 4; i += 512)
        ((float4*)sW)[i] = ((const float4*)Wg)[i];

    int lane = tid & 31, w = tid >> 5;
    int og = (w & (OGW - 1)) * 4 + (lane & 3);
    int eg = (w / OGW) * 8 + (lane >> 2);

    auto stage = [&](long t, int c, int b) {
        float* dst = sX + b * (128 * PC);
        constexpr int UN = 128 * (KC / 4);
        for (int i = tid; i < UN; i += 512) {
            int e_l = i / (KC / 4);
            int ks  = (i % (KC / 4)) * 4;
            cpa16(dst + e_l * PC + ks, op.src(t * 128 + e_l, c * KC + ks));
        }
        cp_commit();
    };

    long t0 = blockIdx.x;
    if (t0 < ntiles) stage(t0, 0, 0);
    int b = 0;

    for (long t = t0; t < ntiles; t += gridDim.x) {
        ULL acc[EPT][NP];
#pragma unroll
        for (int j = 0; j < EPT; j++)
#pragma unroll
            for (int p = 0; p < NP; p++) acc[j][p] = 0ULL;

        for (int c = 0; c < NCH; c++) {
            long nt = t; int nc = c + 1;
            if (nc == NCH) { nt = t + gridDim.x; nc = 0; }
            bool hn = nt < ntiles;
            __syncthreads();                 // prior compute done before overwrite
            if (hn) stage(nt, nc, b ^ 1);
            if (hn) cp_wait1(); else cp_wait0();
            __syncthreads();                 // current buffer visible to all

            const float* Xb = sX + b * (128 * PC);
            const float* xr[EPT];
#pragma unroll
            for (int j = 0; j < EPT; j++) xr[j] = Xb + (eg + EGN * j) * PC;

#pragma unroll 2
            for (int k4 = 0; k4 < KC; k4 += 4) {
                float4 xv[EPT];
#pragma unroll
                for (int j = 0; j < EPT; j++)
                    xv[j] = *(const float4*)(xr[j] + k4);
#pragma unroll
                for (int kk = 0; kk < 4; kk++) {
                    const float* wr = sW + (c * KC + k4 + kk) * OUT + og * OPO;
                    ULL wv[NP];
#pragma unroll
                    for (int p = 0; p < NP; p++)
                        wv[p] = *(const ULL*)(wr + 2 * p);
#pragma unroll
                    for (int j = 0; j < EPT; j++) {
                        float xs = (kk == 0) ? xv[j].x : (kk == 1) ? xv[j].y
                                 : (kk == 2) ? xv[j].z : xv[j].w;
                        ULL xd = pack2(xs);
#pragma unroll
                        for (int p = 0; p < NP; p++)
                            acc[j][p] = fma2(xd, wv[p], acc[j][p]);
                    }
                }
            }
            b ^= 1;
        }

#pragma unroll
        for (int j = 0; j < EPT; j++) {
            long e = t * 128 + eg + EGN * j;
            float r[OPO];
#pragma unroll
            for (int p = 0; p < NP; p++) {
                union { ULL u; float2 f; } cv; cv.u = acc[j][p];
                r[2 * p] = cv.f.x; r[2 * p + 1] = cv.f.y;
            }
            op.epi(e, og, r);
        }
    }
}

// ---------------------------------------------------------------------------
// Epilogue / source policies
// ---------------------------------------------------------------------------
struct OpG1 {   // X0(40) -> silu -> H1(64)
    __device__ const float* src(long e, int k) const { return g_X0 + e * 40 + k; }
    __device__ void epi(long e, int og, const float* r) const {
        float4 o = make_float4(silu_f(r[0] * F_RS40), silu_f(r[1] * F_RS40),
                               silu_f(r[2] * F_RS40), silu_f(r[3] * F_RS40));
        *(float4*)(g_H1 + e * 64 + og * 4) = o;
    }
};
struct OpG2 {   // H1(64) -> silu -> H(128)
    __device__ const float* src(long e, int k) const { return g_H1 + e * 64 + k; }
    __device__ void epi(long e, int og, const float* r) const {
        *(float4*)(g_H + e * 128 + og * 8) =
            make_float4(silu_f(r[0] * F_RS64), silu_f(r[1] * F_RS64),
                        silu_f(r[2] * F_RS64), silu_f(r[3] * F_RS64));
        *(float4*)(g_H + e * 128 + og * 8 + 4) =
            make_float4(silu_f(r[4] * F_RS64), silu_f(r[5] * F_RS64),
                        silu_f(r[6] * F_RS64), silu_f(r[7] * F_RS64));
    }
};
struct OpG3 {   // H(128) -> *fcut -> lat(128)
    __device__ const float* src(long e, int k) const { return g_H + e * 128 + k; }
    __device__ void epi(long e, int og, const float* r) const {
        float s = F_RS128 * g_fcut[e];
        *(float4*)(g_lat + e * 128 + og * 8) =
            make_float4(r[0] * s, r[1] * s, r[2] * s, r[3] * s);
        *(float4*)(g_lat + e * 128 + og * 8 + 4) =
            make_float4(r[4] * s, r[5] * s, r[6] * s, r[7] * s);
    }
};
struct OpG4 {   // lat -> w_all(128): outs 0-63 wedge, 64-127 env scatter
    const int* ctr;
    __device__ const float* src(long e, int k) const { return g_lat + e * 128 + k; }
    __device__ void epi(long e, int og, const float* r) const {
        if (og < 8) {
            *(float4*)(g_wedge + e * 64 + og * 8) =
                make_float4(r[0] * F_RS128, r[1] * F_RS128, r[2] * F_RS128, r[3] * F_RS128);
            *(float4*)(g_wedge + e * 64 + og * 8 + 4) =
                make_float4(r[4] * F_RS128, r[5] * F_RS128, r[6] * F_RS128, r[7] * F_RS128);
        } else {
            long c = ctr[e];
            float4 Y = *(const float4*)(g_Y + e * 4);
#pragma unroll
            for (int p = 0; p < 4; p++) {
                int m = (og - 8) * 4 + p;
                float w0 = r[2 * p] * F_RS128, w1 = r[2 * p + 1] * F_RS128;
                red4(g_env + c * 128 + 4 * m, w0, w1 * Y.y, w1 * Y.z, w1 * Y.w);
            }
        }
    }
};
struct OpG5 {   // scal0(64) -> smix(32)
    __device__ const float* src(long e, int k) const { return g_scal0 + e * 64 + k; }
    __device__ void epi(long e, int og, const float* r) const {
        *(float4*)(g_smix + e * 32 + og * 4) =
            make_float4(r[0] * F_RS64, r[1] * F_RS64, r[2] * F_RS64, r[3] * F_RS64);
    }
};
struct OpG6 {   // P(3E,96) -> vmx(3E,32)
    __device__ const float* src(long e, int k) const { return g_P + e * 96 + k; }
    __device__ void epi(long e, int og, const float* r) const {
        *(float4*)(g_vmx + e * 32 + og * 4) =
            make_float4(r[0] * F_RS96, r[1] * F_RS96, r[2] * F_RS96, r[3] * F_RS96);
    }
};
struct OpG7 {   // [lat|scal0](192) -> silu -> H(128)
    __device__ const float* src(long e, int k) const {
        return (k < 128) ? (g_lat + e * 128 + k) : (g_scal0 + e * 64 + (k - 128));
    }
    __device__ void epi(long e, int og, const float* r) const {
        *(float4*)(g_H + e * 128 + og * 8) =
            make_float4(silu_f(r[0] * F_RS192), silu_f(r[1] * F_RS192),
                        silu_f(r[2] * F_RS192), silu_f(r[3] * F_RS192));
        *(float4*)(g_H + e * 128 + og * 8 + 4) =
            make_float4(silu_f(r[4] * F_RS192), silu_f(r[5] * F_RS192),
                        silu_f(r[6] * F_RS192), silu_f(r[7] * F_RS192));
    }
};
struct OpG8 {   // H(128) -> *fcut, residual -> lat
    __device__ const float* src(long e, int k) const { return g_H + e * 128 + k; }
    __device__ void epi(long e, int og, const float* r) const {
        float s = F_C_NEW * F_RS128 * g_fcut[e];
        float4 l0 = *(const float4*)(g_lat + e * 128 + og * 8);
        float4 l1 = *(const float4*)(g_lat + e * 128 + og * 8 + 4);
        *(float4*)(g_lat + e * 128 + og * 8) =
            make_float4(F_C_OLD * l0.x + s * r[0], F_C_OLD * l0.y + s * r[1],
                        F_C_OLD * l0.z + s * r[2], F_C_OLD * l0.w + s * r[3]);
        *(float4*)(g_lat + e * 128 + og * 8 + 4) =
            make_float4(F_C_OLD * l1.x + s * r[4], F_C_OLD * l1.y + s * r[5],
                        F_C_OLD * l1.z + s * r[6], F_C_OLD * l1.w + s * r[7]);
    }
};
struct OpG9 {   // lat -> w_env1(64) -> env1 scatter
    const int* ctr;
    __device__ const float* src(long e, int k) const { return g_lat + e * 128 + k; }
    __device__ void epi(long e, int og, const float* r) const {
        long c = ctr[e];
        float4 Y = *(const float4*)(g_Y + e * 4);
        int m0 = og * 2;
        float w0 = r[0] * F_RS128, w1 = r[1] * F_RS128;
        red4(g_env1 + c * 128 + 4 * m0, w0, w1 * Y.y, w1 * Y.z, w1 * Y.w);
        float w2 = r[2] * F_RS128, w3 = r[3] * F_RS128;
        red4(g_env1 + c * 128 + 4 * (m0 + 1), w2, w3 * Y.y, w3 * Y.z, w3 * Y.w);
    }
};
struct OpG10 {  // [lat|q](192) -> silu -> H(128)
    __device__ const float* src(long e, int k) const {
        return (k < 128) ? (g_lat + e * 128 + k) : (g_q + e * 64 + (k - 128));
    }
    __device__ void epi(long e, int og, const float* r) const {
        *(float4*)(g_H + e * 128 + og * 8) =
            make_float4(silu_f(r[0] * F_RS192), silu_f(r[1] * F_RS192),
                        silu_f(r[2] * F_RS192), silu_f(r[3] * F_RS192));
        *(float4*)(g_H + e * 128 + og * 8 + 4) =
            make_float4(silu_f(r[4] * F_RS192), silu_f(r[5] * F_RS192),
                        silu_f(r[6] * F_RS192), silu_f(r[7] * F_RS192));
    }
};
struct OpG11 {  // H(128) -> *fcut, residual, *isn -> node scatter
    const int* ctr;
    float* out;
    __device__ const float* src(long e, int k) const { return g_H + e * 128 + k; }
    __device__ void epi(long e, int og, const float* r) const {
        long c = ctr[e];
        float s = F_C_NEW * F_RS128 * g_fcut[e];
        float4 l0 = *(const float4*)(g_lat + e * 128 + og * 8);
        float4 l1 = *(const float4*)(g_lat + e * 128 + og * 8 + 4);
        red4(out + c * 128 + og * 8,
             (F_C_OLD * l0.x + s * r[0]) * F_ISN, (F_C_OLD * l0.y + s * r[1]) * F_ISN,
             (F_C_OLD * l0.z + s * r[2]) * F_ISN, (F_C_OLD * l0.w + s * r[3]) * F_ISN);
        red4(out + c * 128 + og * 8 + 4,
             (F_C_OLD * l1.x + s * r[4]) * F_ISN, (F_C_OLD * l1.y + s * r[5]) * F_ISN,
             (F_C_OLD * l1.z + s * r[6]) * F_ISN, (F_C_OLD * l1.w + s * r[7]) * F_ISN);
    }
};

// ---------------------------------------------------------------------------
__global__ void k_zero(float* __restrict__ out)
{
    int i = blockIdx.x * blockDim.x + threadIdx.x;
    int stride = gridDim.x * blockDim.x;
    for (; i < NN * 128; i += stride) {
        g_env[i]  = 0.0f;
        g_env1[i] = 0.0f;
        out[i]    = 0.0f;
    }
}

// kgeo: per-edge geometry, bessel, Y, fcut, X0 rows
__global__ void __launch_bounds__(256) kgeo(
    const float* __restrict__ coords, const float* __restrict__ attrs,
    const int* __restrict__ eidx)
{
    int e = blockIdx.x * 256 + threadIdx.x;
    if (e >= NE) return;
    int snd = eidx[e];
    int c   = eidx[NE + e];
    float dx = coords[c * 3 + 0] - coords[snd * 3 + 0];
    float dy = coords[c * 3 + 1] - coords[snd * 3 + 1];
    float dz = coords[c * 3 + 2] - coords[snd * 3 + 2];
    float r2 = dx * dx + dy * dy + dz * dz + 1e-12f;
    float r  = sqrtf(r2);
    float inv_r = 1.0f / r;
    float u  = r * F_INV_RMAX;
    float u2 = u * u, u3 = u2 * u, u6 = u3 * u3, u7 = u6 * u, u8 = u7 * u;
    float f  = 1.0f - 28.0f * u6 + 48.0f * u7 - 21.0f * u8;
    if (u >= 1.0f) f = 0.0f;
    g_fcut[e] = f;
    *(float4*)(g_Y + e * 4) = make_float4(1.0f, F_SQRT3 * dx * inv_r,
                                          F_SQRT3 * dy * inv_r, F_SQRT3 * dz * inv_r);
    float* X = g_X0 + (long)e * 40;
    const float4* ac = (const float4*)(attrs + c * 16);
    const float4* as = (const float4*)(attrs + snd * 16);
#pragma unroll
    for (int i = 0; i < 4; i++) ((float4*)X)[i] = ac[i];
#pragma unroll
    for (int i = 0; i < 4; i++) ((float4*)(X + 16))[i] = as[i];
    float bi = inv_r * f * F_BESSEL;
#pragma unroll
    for (int n = 0; n < 8; n++)
        X[32 + n] = bi * sinf((n + 1) * F_PI * u);
}

// kp1: products -> scal0 + P rows (warp per edge, lane = m)
__global__ void __launch_bounds__(256) kp1(const int* __restrict__ eidx)
{
    int warp = (blockIdx.x * 256 + threadIdx.x) >> 5;
    int lane = threadIdx.x & 31;
    int nw = gridDim.x * 8;
    for (long e = warp; e < NE; e += nw) {
        long c = eidx[NE + e];
        float2 we = *(const float2*)(g_wedge + e * 64 + 2 * lane);
        float4 en = *(const float4*)(g_env + c * 128 + 4 * lane);
        float4 Y  = *(const float4*)(g_Y + e * 4);
        float fs  = we.x;
        float fv0 = we.y * Y.y, fv1 = we.y * Y.z, fv2 = we.y * Y.w;
        float es  = en.x * F_ISN;
        float ev0 = en.y * F_ISN, ev1 = en.z * F_ISN, ev2 = en.w * F_ISN;
        g_scal0[e * 64 + lane]      = fs * es;
        g_scal0[e * 64 + 32 + lane] = (fv0 * ev0 + fv1 * ev1 + fv2 * ev2) * F_INV_SQRT3;
        float* P0 = g_P + (3 * e + 0) * 96;
        float* P1 = g_P + (3 * e + 1) * 96;
        float* P2 = g_P + (3 * e + 2) * 96;
        P0[lane] = fs * ev0;  P1[lane] = fs * ev1;  P2[lane] = fs * ev2;
        P0[32 + lane] = fv0 * es; P1[32 + lane] = fv1 * es; P2[32 + lane] = fv2 * es;
        P0[64 + lane] = (fv1 * ev2 - fv2 * ev1) * F_INV_SQRT2;
        P1[64 + lane] = (fv2 * ev0 - fv0 * ev2) * F_INV_SQRT2;
        P2[64 + lane] = (fv0 * ev1 - fv1 * ev0) * F_INV_SQRT2;
    }
}

// kp2: q0/q1 from smix, vmx, env1 (warp per edge, lane = m)
__global__ void __launch_bounds__(256) kp2(const int* __restrict__ eidx)
{
    int warp = (blockIdx.x * 256 + threadIdx.x) >> 5;
    int lane = threadIdx.x & 31;
    int nw = gridDim.x * 8;
    for (long e = warp; e < NE; e += nw) {
        long c = eidx[NE + e];
        float4 e1 = *(const float4*)(g_env1 + c * 128 + 4 * lane);
        float sm = g_smix[e * 32 + lane];
        float v0 = g_vmx[(3 * e + 0) * 32 + lane];
        float v1 = g_vmx[(3 * e + 1) * 32 + lane];
        float v2 = g_vmx[(3 * e + 2) * 32 + lane];
        g_q[e * 64 + lane] = sm * e1.x * F_ISN;
        g_q[e * 64 + 32 + lane] =
            (v0 * e1.y + v1 * e1.z + v2 * e1.w) * F_ISN * F_INV_SQRT3;
    }
}

// ---------------------------------------------------------------------------
extern "C" void kernel_launch(void* const* d_in, const int* in_sizes, int n_in,
                              void* d_out, int out_size)
{
    const float* coords = (const float*)d_in[0];
    const float* attrs  = (const float*)d_in[1];
    const int*   eidx   = (const int*)  d_in[2];
    const float* W2b0   = (const float*)d_in[3];
    const float* W2b1   = (const float*)d_in[4];
    const float* W2b2   = (const float*)d_in[5];
    const float* Wenv0  = (const float*)d_in[6];
    const float* Wlat0  = (const float*)d_in[7];
    const float* Wlat1  = (const float*)d_in[8];
    const float* Ws0    = (const float*)d_in[9];
    const float* Wv0    = (const float*)d_in[10];
    const float* Wenv1  = (const float*)d_in[11];
    const float* Wfin0  = (const float*)d_in[12];
    const float* Wfin1  = (const float*)d_in[13];
    float* out = (float*)d_out;
    const int* ctr = eidx + NE;

    // shared sizes: W + 2*128*PC floats
    const size_t sm40_64   = (40 * 64  + 2 * 128 * 44) * 4;   //  55296
    const size_t sm64_128  = (64 * 128 + 2 * 128 * 68) * 4;   // 102400
    const size_t sm128_128 = (128 * 128 + 2 * 128 * 68) * 4;  // 135168
    const size_t sm64_32   = (64 * 32  + 2 * 128 * 68) * 4;   //  77824
    const size_t sm96_32   = (96 * 32  + 2 * 128 * 100) * 4;  // 114688
    const size_t sm192_128 = (192 * 128 + 2 * 128 * 100) * 4; // 200704
    const size_t sm128_64  = (128 * 64 + 2 * 128 * 68) * 4;   // 102400

    cudaFuncSetAttribute(gk<40, 40, 64, 4, OpG1>,    cudaFuncAttributeMaxDynamicSharedMemorySize, (int)sm40_64);
    cudaFuncSetAttribute(gk<64, 64, 128, 8, OpG2>,   cudaFuncAttributeMaxDynamicSharedMemorySize, (int)sm64_128);
    cudaFuncSetAttribute(gk<128, 64, 128, 8, OpG3>,  cudaFuncAttributeMaxDynamicSharedMemorySize, (int)sm128_128);
    cudaFuncSetAttribute(gk<128, 64, 128, 8, OpG4>,  cudaFuncAttributeMaxDynamicSharedMemorySize, (int)sm128_128);
    cudaFuncSetAttribute(gk<64, 64, 32, 4, OpG5>,    cudaFuncAttributeMaxDynamicSharedMemorySize, (int)sm64_32);
    cudaFuncSetAttribute(gk<96, 96, 32, 4, OpG6>,    cudaFuncAttributeMaxDynamicSharedMemorySize, (int)sm96_32);
    cudaFuncSetAttribute(gk<192, 96, 128, 8, OpG7>,  cudaFuncAttributeMaxDynamicSharedMemorySize, (int)sm192_128);
    cudaFuncSetAttribute(gk<128, 64, 128, 8, OpG8>,  cudaFuncAttributeMaxDynamicSharedMemorySize, (int)sm128_128);
    cudaFuncSetAttribute(gk<128, 64, 64, 4, OpG9>,   cudaFuncAttributeMaxDynamicSharedMemorySize, (int)sm128_64);
    cudaFuncSetAttribute(gk<192, 96, 128, 8, OpG10>, cudaFuncAttributeMaxDynamicSharedMemorySize, (int)sm192_128);
    cudaFuncSetAttribute(gk<128, 64, 128, 8, OpG11>, cudaFuncAttributeMaxDynamicSharedMemorySize, (int)sm128_128);

    const int NT  = NE / 128;    // 2500
    const int NT3 = NE3 / 128;   // 7500

    k_zero<<<512, 256>>>(out);
    kgeo<<<(NE + 255) / 256, 256>>>(coords, attrs, eidx);

    gk<40, 40, 64, 4, OpG1><<<148, 512, sm40_64>>>(OpG1{}, W2b0, NT);
    gk<64, 64, 128, 8, OpG2><<<148, 512, sm64_128>>>(OpG2{}, W2b1, NT);
    gk<128, 64, 128, 8, OpG3><<<148, 512, sm128_128>>>(OpG3{}, W2b2, NT);
    gk<128, 64, 128, 8, OpG4><<<148, 512, sm128_128>>>(OpG4{ctr}, Wenv0, NT);
    kp1<<<640, 256>>>(eidx);
    gk<64, 64, 32, 4, OpG5><<<148, 512, sm64_32>>>(OpG5{}, Ws0, NT);
    gk<96, 96, 32, 4, OpG6><<<148, 512, sm96_32>>>(OpG6{}, Wv0, NT3);
    gk<192, 96, 128, 8, OpG7><<<148, 512, sm192_128>>>(OpG7{}, Wlat0, NT);
    gk<128, 64, 128, 8, OpG8><<<148, 512, sm128_128>>>(OpG8{}, Wlat1, NT);
    gk<128, 64, 64, 4, OpG9><<<148, 512, sm128_64>>>(OpG9{ctr}, Wenv1, NT);
    kp2<<<640, 256>>>(eidx);
    gk<192, 96, 128, 8, OpG10><<<148, 512, sm192_128>>>(OpG10{}, Wfin0, NT);
    gk<128, 64, 128, 8, OpG11><<<148, 512, sm128_128>>>(OpG11{ctr, out}, Wfin1, NT);
}